// round 8
// baseline (speedup 1.0000x reference)
#include <cuda_runtime.h>
#include <cuda_bf16.h>
#include <mma.h>
#include <math.h>
#include <stdint.h>

using namespace nvcuda;

#define BB   8
#define C1   512
#define C2   256
#define SD   512
#define H0   64
#define H1   128
#define NPIX   (H1*H1)      // 16384
#define NPIX0  (H0*H0)      // 4096

// ================= scratch (device globals; no allocation) =================
__device__ float g_s1[BB*C1];
__device__ float g_s2[BB*C2];
__device__ float g_s3[BB*C2];
__device__ float g_e1[BB*C2];
__device__ float g_e2[BB*C2];
__device__ float g_wsq1[C2*C1];
__device__ float g_wsq2[C2*C2];
// bf16 split input tensors: NHWC [b][y][x][3C] = [xhi | xlo | xhi]
__device__ __align__(1024) __nv_bfloat16 g_xc1[(size_t)BB*H1*H1*3*C1]; // 402 MB
__device__ __align__(1024) __nv_bfloat16 g_xc2[(size_t)BB*H1*H1*3*C2]; // 201 MB
// weights [tap][o][3C] = [whi | whi | wlo]
__device__ __align__(1024) __nv_bfloat16 g_w1[(size_t)9*C2*3*C1];
__device__ __align__(1024) __nv_bfloat16 g_w2[(size_t)9*C2*3*C2];

// ================= small prep kernels =================
__global__ void k_styles(const float* __restrict__ w1, const float* __restrict__ w2,
                         const float* __restrict__ m1w, const float* __restrict__ m1b,
                         const float* __restrict__ m2w, const float* __restrict__ m2b,
                         const float* __restrict__ m3w, const float* __restrict__ m3b)
{
    int t = blockIdx.x*blockDim.x + threadIdx.x;
    const float inv = rsqrtf((float)SD);
    if (t < BB*C1) {
        int b = t / C1, i = t % C1;
        float a = 0.f;
        for (int k = 0; k < SD; k++) a += w1[b*SD+k] * m1w[i*SD+k];
        g_s1[t] = a*inv + m1b[i];
    } else if (t < BB*C1 + BB*C2) {
        int u = t - BB*C1; int b = u / C2, i = u % C2;
        float a = 0.f;
        for (int k = 0; k < SD; k++) a += w2[b*SD+k] * m2w[i*SD+k];
        g_s2[u] = a*inv + m2b[i];
    } else if (t < BB*C1 + 2*BB*C2) {
        int u = t - BB*C1 - BB*C2; int b = u / C2, i = u % C2;
        float a = 0.f;
        for (int k = 0; k < SD; k++) a += w2[b*SD+k] * m3w[i*SD+k];
        g_s3[u] = a*inv + m3b[i];
    }
}

__global__ void k_wsq(const float* __restrict__ w1c, const float* __restrict__ w2c)
{
    int t = blockIdx.x*blockDim.x + threadIdx.x;
    if (t < C2*C1) {
        float a = 0.f;
        #pragma unroll
        for (int k = 0; k < 9; k++) { float v = w1c[t*9+k]; a += v*v; }
        g_wsq1[t] = a;
    } else if (t < C2*C1 + C2*C2) {
        int u = t - C2*C1;
        float a = 0.f;
        #pragma unroll
        for (int k = 0; k < 9; k++) { float v = w2c[u*9+k]; a += v*v; }
        g_wsq2[u] = a;
    }
}

__global__ void k_demod()
{
    int t = blockIdx.x*blockDim.x + threadIdx.x;
    const float sc1 = rsqrtf((float)(C1*9));
    const float sc2 = rsqrtf((float)(C2*9));
    if (t < BB*C2) {
        int b = t / C2, o = t % C2;
        float a = 0.f;
        for (int i = 0; i < C1; i++) { float s = g_s1[b*C1+i]; a += g_wsq1[o*C1+i]*s*s; }
        g_e1[t] = sc1 * rsqrtf(sc1*sc1*a + 1e-8f);
    } else if (t < 2*BB*C2) {
        int u = t - BB*C2; int b = u / C2, o = u % C2;
        float a = 0.f;
        for (int i = 0; i < C2; i++) { float s = g_s2[b*C2+i]; a += g_wsq2[o*C2+i]*s*s; }
        g_e2[u] = sc2 * rsqrtf(sc2*sc2*a + 1e-8f);
    }
}

// weight prep: Wcat[tap][o][3CI] = [whi | whi | wlo]
__global__ void k_wprep(const float* __restrict__ w, __nv_bfloat16* __restrict__ wc, int CI)
{
    int t = blockIdx.x*blockDim.x + threadIdx.x;
    if (t >= 9*256*CI) return;
    int ci = t % CI, o = (t/CI) % 256, tap = t/(CI*256);
    float v = w[((size_t)o*CI + ci)*9 + tap];
    __nv_bfloat16 hi = __float2bfloat16(v);
    __nv_bfloat16 lo = __float2bfloat16(v - __bfloat162float(hi));
    size_t base = ((size_t)tap*256 + o)*(size_t)(3*CI);
    wc[base + ci] = hi;
    wc[base + CI + ci] = hi;
    wc[base + 2*CI + ci] = lo;
}

// upsample 2x (half-pixel, clamped) * s1, split to [hi|lo|hi] NHWC bf16
__global__ void k_upsplit(const float* __restrict__ x)
{
    __shared__ float sIn[2][64][64];
    int blk = blockIdx.x;           // b*128 + Y
    int b = blk >> 7, Y = blk & 127;
    int t = threadIdx.x;            // 256
    float sy = Y*0.5f - 0.25f;
    int y0 = (int)floorf(sy); float fy = sy - (float)y0;
    int y0c = max(y0, 0), y1c = min(y0+1, H0-1);
    int xo = t >> 1, cs = (t & 1) * 32;
    float sx = xo*0.5f - 0.25f;
    int x0 = (int)floorf(sx); float fx = sx - (float)x0;
    int x0c = max(x0, 0), x1c = min(x0+1, H0-1);
    float w00 = (1.f-fy)*(1.f-fx), w01 = (1.f-fy)*fx, w10 = fy*(1.f-fx), w11 = fy*fx;
    size_t obase = (((size_t)blk)*H1 + xo)*(size_t)(3*C1);
    for (int cc = 0; cc < 8; cc++) {
        int c0 = cc*64;
        __syncthreads();
        for (int idx = t; idx < 2*64*64; idx += 256) {
            int yr = idx >> 12, c = (idx >> 6) & 63, xs = idx & 63;
            sIn[yr][c][xs] = x[(((size_t)b*C1 + c0 + c)*H0 + (yr ? y1c : y0c))*H0 + xs];
        }
        __syncthreads();
        for (int k = 0; k < 32; k++) {
            int c = cs + k;
            float v = w00*sIn[0][c][x0c] + w01*sIn[0][c][x1c]
                    + w10*sIn[1][c][x0c] + w11*sIn[1][c][x1c];
            v *= g_s1[b*C1 + c0 + c];
            __nv_bfloat16 hi = __float2bfloat16(v);
            __nv_bfloat16 lo = __float2bfloat16(v - __bfloat162float(hi));
            g_xc1[obase + c0 + c]          = hi;
            g_xc1[obase + C1 + c0 + c]     = lo;
            g_xc1[obase + 2*C1 + c0 + c]   = hi;
        }
    }
}

// ================= wmma bf16 implicit-GEMM 3x3 conv =================
// CTA: M=128 o-chans x N=128 pixels (one image row y). K over (3CIN/64) chunks x 9 taps.
// 8 warps: warp (wm 0..3, wn 0..1) computes 32o x 64p -> acc frags [2][4].
// smem: sB [3 ky][132 px][64 k] bf16 (50688 B), sA [2 buf][128 o][64 k] bf16 (32768 B)
//       sC [128][132] fp32 (67584 B) overlaps sB/sA after mainloop.
#define SB_PLANE (132*64)
#define SA_ELEMS (128*64)
#define CONV_SMEM 83456

template<int C3, bool TO_BF16>
__global__ void __launch_bounds__(256, 2)
k_conv(const __nv_bfloat16* __restrict__ xc, const __nv_bfloat16* __restrict__ wc,
       const float* __restrict__ emod, const float* __restrict__ smod,
       const float* __restrict__ noise, const float* __restrict__ nw,
       float* __restrict__ outf, __nv_bfloat16* __restrict__ outb)
{
    extern __shared__ char smem[];
    __nv_bfloat16* sB = (__nv_bfloat16*)smem;               // 3*132*64
    __nv_bfloat16* sA = (__nv_bfloat16*)(smem + 50688);     // 2*128*64
    float*         sC = (float*)smem;                        // 128*132

    constexpr int NCH = C3/64;
    int tid = threadIdx.x;
    int warp = tid >> 5;
    int wm = warp >> 1, wn = warp & 1;
    int y = blockIdx.x, o0 = blockIdx.y*128, b = blockIdx.z;

    // zero halo pixel columns (pp=0,129,130,131) in ALL 3 ky planes
    for (int i = tid; i < 768; i += 256) {
        int ky = i >> 8, r = (i >> 6) & 3, kk = i & 63;
        const int ppz[4] = {0, 129, 130, 131};
        sB[ky*SB_PLANE + ppz[r]*64 + kk] = __float2bfloat16(0.f);
    }

    wmma::fragment<wmma::accumulator, 16, 16, 16, float> acc[2][4];
    #pragma unroll
    for (int i = 0; i < 2; i++)
        #pragma unroll
        for (int j = 0; j < 4; j++) wmma::fill_fragment(acc[i][j], 0.f);

    for (int c = 0; c < NCH; c++) {
        __syncthreads();
        // load B: 3 ky row planes, [p+1][k], zero OOB rows
        for (int i = tid; i < 3*128*8; i += 256) {
            int ky = i >> 10, rem = i & 1023;
            int p = rem >> 3, v = rem & 7;
            int gy = y + ky - 1;
            uint4 val = make_uint4(0u, 0u, 0u, 0u);
            if (gy >= 0 && gy < H1)
                val = *(const uint4*)(xc + (((size_t)(b*H1 + gy))*H1 + p)*C3 + c*64 + v*8);
            *(uint4*)(sB + ky*SB_PLANE + (p+1)*64 + v*8) = val;
        }
        // load A tap 0 into buffer 0
        {
            const __nv_bfloat16* src = wc + ((size_t)0*256 + o0)*C3 + c*64;
            for (int i = tid; i < 128*8; i += 256) {
                int o = i >> 3, v = i & 7;
                *(uint4*)(sA + o*64 + v*8) = *(const uint4*)(src + (size_t)o*C3 + v*8);
            }
        }
        __syncthreads();

        for (int tap = 0; tap < 9; tap++) {
            if (tap < 8) {
                const __nv_bfloat16* src = wc + ((size_t)(tap+1)*256 + o0)*C3 + c*64;
                __nv_bfloat16* dst = sA + ((tap+1)&1)*SA_ELEMS;
                for (int i = tid; i < 128*8; i += 256) {
                    int o = i >> 3, v = i & 7;
                    *(uint4*)(dst + o*64 + v*8) = *(const uint4*)(src + (size_t)o*C3 + v*8);
                }
            }
            int ky = tap/3, kx = tap%3;
            const __nv_bfloat16* pa = sA + (tap&1)*SA_ELEMS + (wm*32)*64;
            const __nv_bfloat16* pb = sB + ky*SB_PLANE + (wn*64 + kx)*64;
            #pragma unroll
            for (int kt = 0; kt < 4; kt++) {
                wmma::fragment<wmma::matrix_a, 16, 16, 16, __nv_bfloat16, wmma::row_major> af0, af1;
                wmma::load_matrix_sync(af0, pa + kt*16, 64);
                wmma::load_matrix_sync(af1, pa + 16*64 + kt*16, 64);
                #pragma unroll
                for (int nf = 0; nf < 4; nf++) {
                    wmma::fragment<wmma::matrix_b, 16, 16, 16, __nv_bfloat16, wmma::col_major> bf;
                    wmma::load_matrix_sync(bf, pb + nf*16*64 + kt*16, 64);
                    wmma::mma_sync(acc[0][nf], af0, bf, acc[0][nf]);
                    wmma::mma_sync(acc[1][nf], af1, bf, acc[1][nf]);
                }
            }
            __syncthreads();
        }
    }

    // drain to sC (overlaps sB/sA)
    #pragma unroll
    for (int i = 0; i < 2; i++)
        #pragma unroll
        for (int nf = 0; nf < 4; nf++)
            wmma::store_matrix_sync(sC + (wm*32 + i*16)*132 + wn*64 + nf*16,
                                    acc[i][nf], 132, wmma::mem_row_major);
    __syncthreads();

    float nwv = nw[0];
    for (int i = tid; i < 128*128; i += 256) {
        int oo, p;
        if (TO_BF16) { oo = i & 127; p = i >> 7; }   // consecutive threads -> consecutive o
        else         { oo = i >> 7; p = i & 127; }   // consecutive threads -> consecutive p
        int o = o0 + oo;
        float e = emod[b*C2 + o];
        float v = sC[oo*132 + p]*e + nwv*noise[((size_t)b << 14) + (y << 7) + p];
        v = (v > 0.f) ? v : 0.2f*v;
        if (TO_BF16) {
            float vm = v * smod[b*C2 + o];
            __nv_bfloat16 hi = __float2bfloat16(vm);
            __nv_bfloat16 lo = __float2bfloat16(vm - __bfloat162float(hi));
            size_t pb = (((size_t)(b*H1 + y))*H1 + p)*(size_t)(3*C2);
            outb[pb + o]        = hi;
            outb[pb + C2 + o]   = lo;
            outb[pb + 2*C2 + o] = hi;
        } else {
            outf[((size_t)(b*C2 + o) << 14) + (y << 7) + p] = v;
        }
    }
}

// ================= to_rgb 1x1 + upsampled skip =================
__global__ void k_rgb(const float* __restrict__ h, const float* __restrict__ rgbw,
                      const float* __restrict__ skip, float* __restrict__ outrgb)
{
    int b = blockIdx.y;
    __shared__ float sw[3][C2];
    for (int i = threadIdx.x; i < 3*C2; i += blockDim.x) {
        int c = i / C2, o = i % C2;
        sw[c][o] = rgbw[c*C2 + o] * g_s3[b*C2 + o] * 0.0625f;  // 1/sqrt(256)
    }
    __syncthreads();
    int p = blockIdx.x*blockDim.x + threadIdx.x;
    float a0 = 0.f, a1 = 0.f, a2 = 0.f;
    for (int o = 0; o < C2; o++) {
        float v = h[(size_t)(b*C2 + o)*NPIX + p];
        a0 += sw[0][o]*v; a1 += sw[1][o]*v; a2 += sw[2][o]*v;
    }
    int X = p % H1, Y = p / H1;
    float sy = Y*0.5f - 0.25f, sx = X*0.5f - 0.25f;
    int y0 = (int)floorf(sy), x0 = (int)floorf(sx);
    float fy = sy - (float)y0, fx = sx - (float)x0;
    int y0c = max(y0, 0), y1c = min(y0+1, H0-1);
    int x0c = max(x0, 0), x1c = min(x0+1, H0-1);
    float a[3] = {a0, a1, a2};
    #pragma unroll
    for (int c = 0; c < 3; c++) {
        const float* sp = skip + (size_t)(b*3 + c)*NPIX0;
        float bv = (1.f-fy)*((1.f-fx)*sp[y0c*H0+x0c] + fx*sp[y0c*H0+x1c])
                 +      fy *((1.f-fx)*sp[y1c*H0+x0c] + fx*sp[y1c*H0+x1c]);
        outrgb[(size_t)(b*3 + c)*NPIX + p] = a[c] + bv;
    }
}

// ================= host =================
extern "C" void kernel_launch(void* const* d_in, const int* in_sizes, int n_in,
                              void* d_out, int out_size)
{
    const float* x       = (const float*)d_in[0];
    const float* w1      = (const float*)d_in[1];
    const float* w2      = (const float*)d_in[2];
    const float* skip    = (const float*)d_in[3];
    const float* noise1  = (const float*)d_in[4];
    const float* noise2  = (const float*)d_in[5];
    const float* conv1_w = (const float*)d_in[6];
    const float* mod1_w  = (const float*)d_in[7];
    const float* mod1_b  = (const float*)d_in[8];
    const float* conv2_w = (const float*)d_in[9];
    const float* mod2_w  = (const float*)d_in[10];
    const float* mod2_b  = (const float*)d_in[11];
    const float* rgb_w   = (const float*)d_in[12];
    const float* mod3_w  = (const float*)d_in[13];
    const float* mod3_b  = (const float*)d_in[14];
    const float* nw1     = (const float*)d_in[15];
    const float* nw2     = (const float*)d_in[16];
    float* out = (float*)d_out;

    void *p_xc1, *p_xc2, *p_w1, *p_w2, *p_e1, *p_e2, *p_s2;
    cudaGetSymbolAddress(&p_xc1, g_xc1);
    cudaGetSymbolAddress(&p_xc2, g_xc2);
    cudaGetSymbolAddress(&p_w1, g_w1);
    cudaGetSymbolAddress(&p_w2, g_w2);
    cudaGetSymbolAddress(&p_e1, g_e1);
    cudaGetSymbolAddress(&p_e2, g_e2);
    cudaGetSymbolAddress(&p_s2, g_s2);

    cudaFuncSetAttribute(k_conv<3*C1, true >, cudaFuncAttributeMaxDynamicSharedMemorySize, CONV_SMEM);
    cudaFuncSetAttribute(k_conv<3*C2, false>, cudaFuncAttributeMaxDynamicSharedMemorySize, CONV_SMEM);

    float* out_h   = out;                          // [8,256,128,128]
    float* out_rgb = out + (size_t)BB*C2*NPIX;     // [8,3,128,128]

    // 1. styles
    {
        int n = BB*C1 + 2*BB*C2;
        k_styles<<<(n + 255)/256, 256>>>(w1, w2, mod1_w, mod1_b, mod2_w, mod2_b, mod3_w, mod3_b);
    }
    // 2. weight square sums + demod scalars
    {
        int n = C2*C1 + C2*C2;
        k_wsq<<<(n + 255)/256, 256>>>(conv1_w, conv2_w);
    }
    k_demod<<<(2*BB*C2 + 255)/256, 256>>>();
    // 3. bf16 split weight prep
    k_wprep<<<(9*256*C1 + 255)/256, 256>>>(conv1_w, (__nv_bfloat16*)p_w1, C1);
    k_wprep<<<(9*256*C2 + 255)/256, 256>>>(conv2_w, (__nv_bfloat16*)p_w2, C2);
    // 4. upsample + modulate(s1) + bf16 split -> g_xc1
    k_upsplit<<<BB*H1, 256>>>(x);
    // 5. conv1 (wmma) -> g_xc2 (modulated by s2, bf16 split NHWC)
    k_conv<3*C1, true ><<<dim3(H1, 2, BB), 256, CONV_SMEM>>>(
        (const __nv_bfloat16*)p_xc1, (const __nv_bfloat16*)p_w1,
        (const float*)p_e1, (const float*)p_s2, noise1, nw1, nullptr, (__nv_bfloat16*)p_xc2);
    // 6. conv2 (wmma) -> d_out h region (fp32 NCHW)
    k_conv<3*C2, false><<<dim3(H1, 2, BB), 256, CONV_SMEM>>>(
        (const __nv_bfloat16*)p_xc2, (const __nv_bfloat16*)p_w2,
        (const float*)p_e2, (const float*)p_s2, noise2, nw2, out_h, nullptr);
    // 7. to_rgb + upsampled skip
    k_rgb<<<dim3(NPIX/256, BB), 256>>>(out_h, rgb_w, skip, out_rgb);
}

// round 9
// speedup vs baseline: 1.7073x; 1.7073x over previous
#include <cuda_runtime.h>
#include <math.h>
#include <stdint.h>

#define BB   8
#define C1   512
#define C2   256
#define SD   512
#define H0   64
#define H1   128
#define NPIX   (H1*H1)      // 16384
#define NPIX0  (H0*H0)      // 4096

typedef unsigned long long ull;

// packed f32x2 helpers (sm_100+ PTX)
__device__ __forceinline__ void ffma2(ull& acc, ull a, ull b) {
    asm("fma.rn.f32x2 %0, %1, %2, %0;" : "+l"(acc) : "l"(a), "l"(b));
}
__device__ __forceinline__ ull bcast2(float v) {
    ull p;
    asm("mov.b64 %0, {%1, %1};" : "=l"(p) : "r"(__float_as_uint(v)));
    return p;
}
__device__ __forceinline__ void unpack2(ull p, float& lo, float& hi) {
    unsigned int a, b;
    asm("mov.b64 {%0, %1}, %2;" : "=r"(a), "=r"(b) : "l"(p));
    lo = __uint_as_float(a); hi = __uint_as_float(b);
}

// ---------------- scratch (device globals; no allocation) ----------------
__device__ float g_s1[BB*C1];
__device__ float g_s2[BB*C2];
__device__ float g_s3[BB*C2];
__device__ float g_e1[BB*C2];
__device__ float g_e2[BB*C2];
__device__ float g_wsq1[C2*C1];
__device__ float g_wsq2[C2*C2];
__device__ float g_h1 [(size_t)BB*C2*NPIX];   // 134 MB

// ---------------- styles ----------------
__global__ void k_styles(const float* __restrict__ w1, const float* __restrict__ w2,
                         const float* __restrict__ m1w, const float* __restrict__ m1b,
                         const float* __restrict__ m2w, const float* __restrict__ m2b,
                         const float* __restrict__ m3w, const float* __restrict__ m3b)
{
    int t = blockIdx.x*blockDim.x + threadIdx.x;
    const float inv = rsqrtf((float)SD);
    if (t < BB*C1) {
        int b = t / C1, i = t % C1;
        float a = 0.f;
        for (int k = 0; k < SD; k++) a += w1[b*SD+k] * m1w[i*SD+k];
        g_s1[t] = a*inv + m1b[i];
    } else if (t < BB*C1 + BB*C2) {
        int u = t - BB*C1; int b = u / C2, i = u % C2;
        float a = 0.f;
        for (int k = 0; k < SD; k++) a += w2[b*SD+k] * m2w[i*SD+k];
        g_s2[u] = a*inv + m2b[i];
    } else if (t < BB*C1 + 2*BB*C2) {
        int u = t - BB*C1 - BB*C2; int b = u / C2, i = u % C2;
        float a = 0.f;
        for (int k = 0; k < SD; k++) a += w2[b*SD+k] * m3w[i*SD+k];
        g_s3[u] = a*inv + m3b[i];
    }
}

// ---------------- per-(o,i) sum of squared 3x3 taps ----------------
__global__ void k_wsq(const float* __restrict__ w1c, const float* __restrict__ w2c)
{
    int t = blockIdx.x*blockDim.x + threadIdx.x;
    if (t < C2*C1) {
        float a = 0.f;
        #pragma unroll
        for (int k = 0; k < 9; k++) { float v = w1c[t*9+k]; a += v*v; }
        g_wsq1[t] = a;
    } else if (t < C2*C1 + C2*C2) {
        int u = t - C2*C1;
        float a = 0.f;
        #pragma unroll
        for (int k = 0; k < 9; k++) { float v = w2c[u*9+k]; a += v*v; }
        g_wsq2[u] = a;
    }
}

// ---------------- demod scalars ----------------
__global__ void k_demod()
{
    int t = blockIdx.x*blockDim.x + threadIdx.x;
    const float sc1 = rsqrtf((float)(C1*9));
    const float sc2 = rsqrtf((float)(C2*9));
    if (t < BB*C2) {
        int b = t / C2, o = t % C2;
        float a = 0.f;
        for (int i = 0; i < C1; i++) { float s = g_s1[b*C1+i]; a += g_wsq1[o*C1+i]*s*s; }
        g_e1[t] = sc1 * rsqrtf(sc1*sc1*a + 1e-8f);
    } else if (t < 2*BB*C2) {
        int u = t - BB*C2; int b = u / C2, o = u % C2;
        float a = 0.f;
        for (int i = 0; i < C2; i++) { float s = g_s2[b*C2+i]; a += g_wsq2[o*C2+i]*s*s; }
        g_e2[u] = sc2 * rsqrtf(sc2*sc2*a + 1e-8f);
    }
}

// ---------------- 3x3 conv, pad 1, FFMA2 inner loop ----------------
// CTA: 32 o-chans x (32x8) pixels. 128 threads: po=tid/32 (8 o each), tx=tid%32.
// UPIN=true: input is 64x64 x; fill stages coarse tile then expands bilinear*s1.
// UPIN=false: input is 128x128 NCHW (g_h1), modulated by s2 at load.
#define KC 16
#define TO 32
// dynamic smem layout (floats):
//   sW   [KC][9][34]   : 4896
//   sIn  [KC][10][34]  : 5440   @ 4896
//   sC0  [KC][6][20]   : 1920   @ 10336 (UPIN only)
//   sSm  [KC]          : @ 12256 (UPIN) / 10336 (else)
#define SMEM_F_UP   (12256 + KC)
#define SMEM_F_DIR  (10336 + KC)

template<int CIN, bool UPIN>
__global__ void __launch_bounds__(128, 4)
k_conv3x3(const float* __restrict__ in, const float* __restrict__ wgt,
          const float* __restrict__ smod, const float* __restrict__ emod,
          const float* __restrict__ noise, const float* __restrict__ nw,
          float* __restrict__ out)
{
    extern __shared__ float smem[];
    float* sW  = smem;                 // [KC][9][34]
    float* sIn = smem + 4896;          // [KC][10][34]
    float* sC0 = smem + 10336;         // [KC][6][20]
    float* sSm = smem + (UPIN ? 12256 : 10336);

    int tid = threadIdx.x;
    int po  = tid >> 5;
    int tx  = tid & 31;
    int bz  = blockIdx.z;
    int b   = bz >> 3;
    int o0  = (bz & 7) * TO;
    int gx0 = blockIdx.x * 32;
    int gy0 = blockIdx.y * 8;
    int cy0 = (gy0 >> 1) - 1;
    int cx0 = (gx0 >> 1) - 1;

    ull acc2[4][8];
    #pragma unroll
    for (int q = 0; q < 4; q++)
        #pragma unroll
        for (int j = 0; j < 8; j++) acc2[q][j] = 0ULL;

    for (int ci0 = 0; ci0 < CIN; ci0 += KC) {
        __syncthreads();
        if (tid < KC) sSm[tid] = smod[b*CIN + ci0 + tid];
        // weights: sW[c][tp][o]
        for (int idx = tid; idx < TO*KC*9; idx += 128) {
            int o = idx / (KC*9), rem = idx % (KC*9);
            int c = rem / 9, tp = rem % 9;
            sW[(c*9 + tp)*34 + o] = wgt[(size_t)((o0 + o)*CIN + ci0 + c)*9 + tp];
        }
        if (UPIN) {
            // stage coarse 6x20 (clamped) per channel
            for (int idx = tid; idx < KC*6*20; idx += 128) {
                int c = idx / 120, rem = idx % 120;
                int ry = rem / 20, cx = rem % 20;
                int gyc = min(max(cy0 + ry, 0), H0-1);
                int gxc = min(max(cx0 + cx, 0), H0-1);
                sC0[idx] = in[((size_t)(b*C1 + ci0 + c)*H0 + gyc)*H0 + gxc];
            }
            __syncthreads();
            // expand bilinear * s1 into fine tile (zero outside image = conv pad)
            for (int idx = tid; idx < KC*10*34; idx += 128) {
                int c = idx / 340, rem = idx % 340;
                int r = rem / 34, col = rem % 34;
                int gy = gy0 + r - 1, gx = gx0 + col - 1;
                float v = 0.f;
                if ((unsigned)gy < H1 && (unsigned)gx < H1) {
                    float syf = gy*0.5f - 0.25f, sxf = gx*0.5f - 0.25f;
                    int iy = (int)floorf(syf), ix = (int)floorf(sxf);
                    float fy = syf - (float)iy, fx = sxf - (float)ix;
                    const float* p = &sC0[(c*6 + (iy - cy0))*20 + (ix - cx0)];
                    v = (1.f-fy)*((1.f-fx)*p[0]  + fx*p[1])
                      +      fy *((1.f-fx)*p[20] + fx*p[21]);
                    v *= sSm[c];
                }
                sIn[idx] = v;
            }
        } else {
            for (int idx = tid; idx < KC*10*34; idx += 128) {
                int c = idx / 340, rem = idx % 340;
                int r = rem / 34, col = rem % 34;
                int gy = gy0 + r - 1, gx = gx0 + col - 1;
                float v = 0.f;
                if ((unsigned)gy < H1 && (unsigned)gx < H1)
                    v = in[(size_t)(b*CIN + ci0 + c)*NPIX + gy*H1 + gx] * sSm[c];
                sIn[idx] = v;
            }
        }
        __syncthreads();

        #pragma unroll 1
        for (int c = 0; c < KC; c++) {
            const float* pI = sIn + c*340;
            const float* pW = sW + c*306;
            #pragma unroll
            for (int kx = 0; kx < 3; kx++) {
                ull vb[10];
                #pragma unroll
                for (int r = 0; r < 10; r++) vb[r] = bcast2(pI[r*34 + tx + kx]);
                #pragma unroll
                for (int ky = 0; ky < 3; ky++) {
                    ull wp[4];
                    #pragma unroll
                    for (int q = 0; q < 4; q++)
                        wp[q] = *reinterpret_cast<const ull*>(&pW[(ky*3+kx)*34 + po*8 + q*2]);
                    #pragma unroll
                    for (int q = 0; q < 4; q++)
                        #pragma unroll
                        for (int j = 0; j < 8; j++)
                            ffma2(acc2[q][j], wp[q], vb[ky + j]);
                }
            }
        }
    }

    float nwv = nw[0];
    #pragma unroll
    for (int j = 0; j < 8; j++) {
        int gy = gy0 + j, gx = gx0 + tx;
        float nz = nwv * noise[(size_t)b*NPIX + gy*H1 + gx];
        #pragma unroll
        for (int q = 0; q < 4; q++) {
            int o = o0 + po*8 + q*2;
            float a0, a1; unpack2(acc2[q][j], a0, a1);
            float e0 = emod[b*C2 + o], e1 = emod[b*C2 + o + 1];
            float v0 = a0*e0 + nz; v0 = (v0 > 0.f) ? v0 : 0.2f*v0;
            float v1 = a1*e1 + nz; v1 = (v1 > 0.f) ? v1 : 0.2f*v1;
            out[(size_t)(b*C2 + o    )*NPIX + gy*H1 + gx] = v0;
            out[(size_t)(b*C2 + o + 1)*NPIX + gy*H1 + gx] = v1;
        }
    }
}

// ---------------- to_rgb 1x1 (no demod) + upsampled skip ----------------
__global__ void k_rgb(const float* __restrict__ h, const float* __restrict__ rgbw,
                      const float* __restrict__ skip, float* __restrict__ outrgb)
{
    int b = blockIdx.y;
    __shared__ float sw[3][C2];
    for (int i = threadIdx.x; i < 3*C2; i += blockDim.x) {
        int c = i / C2, o = i % C2;
        sw[c][o] = rgbw[c*C2 + o] * g_s3[b*C2 + o] * 0.0625f;  // 1/sqrt(256)
    }
    __syncthreads();
    int p = blockIdx.x*blockDim.x + threadIdx.x;  // 64*256 = 16384 exact
    float a0 = 0.f, a1 = 0.f, a2 = 0.f;
    for (int o = 0; o < C2; o++) {
        float v = h[(size_t)(b*C2 + o)*NPIX + p];
        a0 += sw[0][o]*v; a1 += sw[1][o]*v; a2 += sw[2][o]*v;
    }
    int X = p % H1, Y = p / H1;
    float sy = Y*0.5f - 0.25f, sx = X*0.5f - 0.25f;
    int y0 = (int)floorf(sy), x0 = (int)floorf(sx);
    float fy = sy - (float)y0, fx = sx - (float)x0;
    int y0c = max(y0, 0), y1c = min(y0+1, H0-1);
    int x0c = max(x0, 0), x1c = min(x0+1, H0-1);
    float a[3] = {a0, a1, a2};
    #pragma unroll
    for (int c = 0; c < 3; c++) {
        const float* sp = skip + (size_t)(b*3 + c)*NPIX0;
        float bv = (1.f-fy)*((1.f-fx)*sp[y0c*H0+x0c] + fx*sp[y0c*H0+x1c])
                 +      fy *((1.f-fx)*sp[y1c*H0+x0c] + fx*sp[y1c*H0+x1c]);
        outrgb[(size_t)(b*3 + c)*NPIX + p] = a[c] + bv;
    }
}

// ---------------- launch ----------------
extern "C" void kernel_launch(void* const* d_in, const int* in_sizes, int n_in,
                              void* d_out, int out_size)
{
    const float* x       = (const float*)d_in[0];
    const float* w1      = (const float*)d_in[1];
    const float* w2      = (const float*)d_in[2];
    const float* skip    = (const float*)d_in[3];
    const float* noise1  = (const float*)d_in[4];
    const float* noise2  = (const float*)d_in[5];
    const float* conv1_w = (const float*)d_in[6];
    const float* mod1_w  = (const float*)d_in[7];
    const float* mod1_b  = (const float*)d_in[8];
    const float* conv2_w = (const float*)d_in[9];
    const float* mod2_w  = (const float*)d_in[10];
    const float* mod2_b  = (const float*)d_in[11];
    const float* rgb_w   = (const float*)d_in[12];
    const float* mod3_w  = (const float*)d_in[13];
    const float* mod3_b  = (const float*)d_in[14];
    const float* nw1     = (const float*)d_in[15];
    const float* nw2     = (const float*)d_in[16];
    float* out = (float*)d_out;

    void *p_h1, *p_e1, *p_e2, *p_s1, *p_s2;
    cudaGetSymbolAddress(&p_h1, g_h1);
    cudaGetSymbolAddress(&p_e1, g_e1);
    cudaGetSymbolAddress(&p_e2, g_e2);
    cudaGetSymbolAddress(&p_s1, g_s1);
    cudaGetSymbolAddress(&p_s2, g_s2);

    const int smem_up  = SMEM_F_UP  * 4;   // 49088 B
    const int smem_dir = SMEM_F_DIR * 4;   // 41408 B
    cudaFuncSetAttribute(k_conv3x3<C1, true >, cudaFuncAttributeMaxDynamicSharedMemorySize, smem_up);
    cudaFuncSetAttribute(k_conv3x3<C2, false>, cudaFuncAttributeMaxDynamicSharedMemorySize, smem_dir);

    float* out_h   = out;                                // [8,256,128,128]
    float* out_rgb = out + (size_t)BB*C2*NPIX;           // [8,3,128,128]

    // 1. styles
    {
        int n = BB*C1 + 2*BB*C2;
        k_styles<<<(n + 255)/256, 256>>>(w1, w2, mod1_w, mod1_b, mod2_w, mod2_b, mod3_w, mod3_b);
    }
    // 2. weight square sums + demod scalars
    {
        int n = C2*C1 + C2*C2;
        k_wsq<<<(n + 255)/256, 256>>>(conv1_w, conv2_w);
    }
    k_demod<<<(2*BB*C2 + 255)/256, 256>>>();
    // 3. conv1: fused upsample(bilinear)+s1-mod + 3x3 conv + noise + lrelu -> g_h1
    k_conv3x3<C1, true ><<<dim3(4, 16, BB*8), 128, smem_up>>>(
        x, conv1_w, (const float*)p_s1, (const float*)p_e1, noise1, nw1, (float*)p_h1);
    // 4. conv2: s2-mod at load + 3x3 conv + noise + lrelu -> d_out h region
    k_conv3x3<C2, false><<<dim3(4, 16, BB*8), 128, smem_dir>>>(
        (const float*)p_h1, conv2_w, (const float*)p_s2, (const float*)p_e2, noise2, nw2, out_h);
    // 5. to_rgb + upsampled skip -> d_out rgb region
    k_rgb<<<dim3(NPIX/256, BB), 256>>>(out_h, rgb_w, skip, out_rgb);
}